// round 15
// baseline (speedup 1.0000x reference)
#include <cuda_runtime.h>
#include <cuda_bf16.h>
#include <cuda_fp16.h>
#include <cstdint>

// ---------------- problem constants ----------------
#define N_NODES 50000
#define N_EDGES 800000
#define HID 256
#define HEADS 8
#define NEG_SLOPE 0.2f

// ---------------- device scratch (static, no allocation) ----------------
__device__ __half g_feat16[(size_t)N_NODES * HID];         // x @ W messages (fp16)
__device__ __nv_bfloat16 g_Ah[(size_t)N_NODES * HID];      // GEMM A operand, bf16 high
__device__ __nv_bfloat16 g_Al[(size_t)N_NODES * HID];      // GEMM A operand, bf16 low
__device__ __nv_bfloat16 g_W1h[HID * HID];
__device__ __nv_bfloat16 g_W1l[HID * HID];
__device__ __nv_bfloat16 g_W2h[HID * HID];
__device__ __nv_bfloat16 g_W2l[HID * HID];
__device__ float g_el[(size_t)N_NODES * HEADS];
__device__ float g_er[(size_t)N_NODES * HEADS];
__device__ int   g_count[N_NODES];
__device__ int   g_rowoff[N_NODES + 1];
__device__ int   g_fill[N_NODES];
__device__ int   g_srcs[N_EDGES];

// ---------------- helpers ----------------
__device__ __forceinline__ uint32_t smem_u32(const void* p) {
    uint32_t a;
    asm("{ .reg .u64 t; cvta.to.shared.u64 t, %1; cvt.u32.u64 %0, t; }" : "=r"(a) : "l"(p));
    return a;
}

__device__ __forceinline__ void ldsm4(uint32_t* r, uint32_t a) {
    asm volatile("ldmatrix.sync.aligned.m8n8.x4.shared.b16 {%0,%1,%2,%3}, [%4];"
                 : "=r"(r[0]), "=r"(r[1]), "=r"(r[2]), "=r"(r[3]) : "r"(a));
}

__device__ __forceinline__ void ldsm4t(uint32_t* r, uint32_t a) {
    asm volatile("ldmatrix.sync.aligned.m8n8.x4.trans.shared.b16 {%0,%1,%2,%3}, [%4];"
                 : "=r"(r[0]), "=r"(r[1]), "=r"(r[2]), "=r"(r[3]) : "r"(a));
}

__device__ __forceinline__ void mma_bf16(float* d, const uint32_t* a, const uint32_t* b) {
    asm volatile("mma.sync.aligned.m16n8k16.row.col.f32.bf16.bf16.f32 "
                 "{%0,%1,%2,%3}, {%4,%5,%6,%7}, {%8,%9}, {%0,%1,%2,%3};"
                 : "+f"(d[0]), "+f"(d[1]), "+f"(d[2]), "+f"(d[3])
                 : "r"(a[0]), "r"(a[1]), "r"(a[2]), "r"(a[3]), "r"(b[0]), "r"(b[1]));
}

__device__ __forceinline__ void cp16(uint32_t dst, const void* src, bool valid) {
    int sz = valid ? 16 : 0;
    asm volatile("cp.async.cg.shared.global [%0], [%1], 16, %2;"
                 :: "r"(dst), "l"(src), "r"(sz) : "memory");
}
#define CP_COMMIT() asm volatile("cp.async.commit_group;" ::: "memory")
#define CP_WAIT1()  asm volatile("cp.async.wait_group 1;" ::: "memory")
#define CP_WAIT0()  asm volatile("cp.async.wait_group 0;" ::: "memory")

__device__ __forceinline__ uint32_t pack2(__nv_bfloat16 a, __nv_bfloat16 b) {
    __nv_bfloat162 t; t.x = a; t.y = b;
    return *reinterpret_cast<uint32_t*>(&t);
}

__device__ __forceinline__ float leaky(float x) { return x > 0.f ? x : NEG_SLOPE * x; }

// ---------------- CSR build ----------------
__global__ void zero_count_kernel() {
    int i = blockIdx.x * blockDim.x + threadIdx.x;
    if (i < N_NODES) g_count[i] = 0;
}

__global__ void hist_kernel(const int* __restrict__ dst) {
    int e = blockIdx.x * blockDim.x + threadIdx.x;
    if (e < N_EDGES) atomicAdd(&g_count[dst[e]], 1);
}

__global__ void scan_kernel() {
    __shared__ int sums[1024];
    const int tid = threadIdx.x;
    const int CH = (N_NODES + 1023) / 1024;
    int start = tid * CH;
    int end = start + CH; if (end > N_NODES) end = N_NODES;
    if (start > N_NODES) start = N_NODES;
    int s = 0;
    for (int i = start; i < end; ++i) s += g_count[i];
    sums[tid] = s;
    __syncthreads();
    for (int off = 1; off < 1024; off <<= 1) {
        int v = (tid >= off) ? sums[tid - off] : 0;
        __syncthreads();
        sums[tid] += v;
        __syncthreads();
    }
    int run = (tid == 0) ? 0 : sums[tid - 1];
    for (int i = start; i < end; ++i) {
        int c = g_count[i];
        g_rowoff[i] = run;
        g_fill[i] = run;
        run += c;
    }
    if (tid == 1023) g_rowoff[N_NODES] = run;
}

__global__ void scatter_kernel(const int* __restrict__ src, const int* __restrict__ dst) {
    int e = blockIdx.x * blockDim.x + threadIdx.x;
    if (e < N_EDGES) {
        int p = atomicAdd(&g_fill[dst[e]], 1);
        g_srcs[p] = src[e];
    }
}

// ---------------- fp32 -> bf16 hi/lo split prepass ----------------
__global__ void prep_split_kernel(const float* __restrict__ in,
                                  __nv_bfloat16* __restrict__ hi,
                                  __nv_bfloat16* __restrict__ lo, int n4) {
    int idx = blockIdx.x * blockDim.x + threadIdx.x;
    if (idx >= n4) return;
    float4 x = ((const float4*)in)[idx];
    __nv_bfloat16 hx = __float2bfloat16_rn(x.x);
    __nv_bfloat16 hy = __float2bfloat16_rn(x.y);
    __nv_bfloat16 hz = __float2bfloat16_rn(x.z);
    __nv_bfloat16 hw = __float2bfloat16_rn(x.w);
    uint2 hp = make_uint2(pack2(hx, hy), pack2(hz, hw));
    uint2 lp = make_uint2(
        pack2(__float2bfloat16_rn(x.x - __bfloat162float(hx)),
              __float2bfloat16_rn(x.y - __bfloat162float(hy))),
        pack2(__float2bfloat16_rn(x.z - __bfloat162float(hz)),
              __float2bfloat16_rn(x.w - __bfloat162float(hw))));
    ((uint2*)hi)[idx] = hp;
    ((uint2*)lo)[idx] = lp;
}

// ---------------- HMMA bf16-split GEMM + fused el/er (cp.async 2-stage) ----------------
#define OFF_AH 0
#define OFF_AL 20480
#define OFF_BH 40960
#define OFF_BL 58368
#define GEMM_SMEM 75776

__global__ __launch_bounds__(256) void hgemm_kernel(const float* __restrict__ al,
                                                    const float* __restrict__ ar,
                                                    const __nv_bfloat16* __restrict__ Wh,
                                                    const __nv_bfloat16* __restrict__ Wl) {
    extern __shared__ char sm[];
    const uint32_t sb = smem_u32(sm);

    const int tid = threadIdx.x;
    const int wid = tid >> 5;
    const int lane = tid & 31;
    const int wm = wid >> 2;
    const int wn = wid & 3;
    const int brow = blockIdx.x * 128;
    const int bcol = blockIdx.y * 128;

    float acc[4][4][4];
#pragma unroll
    for (int i = 0; i < 4; ++i)
#pragma unroll
        for (int j = 0; j < 4; ++j)
#pragma unroll
            for (int k = 0; k < 4; ++k) acc[i][j][k] = 0.f;

    const int arow = tid >> 1;
    const int acol = (tid & 1) * 16;
    const int brw = tid >> 3;
    const int bcl = (tid & 7) * 16;

    const bool arow_ok = (brow + arow) < N_NODES;
    const size_t abase = (size_t)(brow + arow) * 256 + acol;

    const int lrow = lane & 15;
    const int lcol = (lane >> 4) << 3;

    auto issue = [&](int c, int st) {
        const int k0 = c * 32;
        uint32_t adst = sb + OFF_AH + st * 10240 + arow * 80 + acol * 2;
        cp16(adst,      &g_Ah[abase + k0],     arow_ok);
        cp16(adst + 16, &g_Ah[abase + k0 + 8], arow_ok);
        uint32_t aldst = sb + OFF_AL + st * 10240 + arow * 80 + acol * 2;
        cp16(aldst,      &g_Al[abase + k0],     arow_ok);
        cp16(aldst + 16, &g_Al[abase + k0 + 8], arow_ok);
        const size_t bbase = (size_t)(k0 + brw) * 256 + bcol + bcl;
        uint32_t bdst = sb + OFF_BH + st * 8704 + brw * 272 + bcl * 2;
        cp16(bdst,      &Wh[bbase],     true);
        cp16(bdst + 16, &Wh[bbase + 8], true);
        uint32_t bldst = sb + OFF_BL + st * 8704 + brw * 272 + bcl * 2;
        cp16(bldst,      &Wl[bbase],     true);
        cp16(bldst + 16, &Wl[bbase + 8], true);
    };

    issue(0, 0);
    CP_COMMIT();

    for (int c = 0; c < 8; ++c) {
        const int st = c & 1;
        if (c < 7) {
            issue(c + 1, st ^ 1);
            CP_COMMIT();
            CP_WAIT1();
        } else {
            CP_WAIT0();
        }
        __syncthreads();

        const uint32_t ah_base = sb + OFF_AH + st * 10240;
        const uint32_t al_base = sb + OFF_AL + st * 10240;
        const uint32_t bh_base = sb + OFF_BH + st * 8704;
        const uint32_t bl_base = sb + OFF_BL + st * 8704;

#pragma unroll
        for (int kk = 0; kk < 2; ++kk) {
            const int k16 = kk * 16;
            uint32_t af[4][4], bh[4][2], bl[4][2];
#pragma unroll
            for (int mi = 0; mi < 4; ++mi)
                ldsm4(af[mi], ah_base + (wm * 64 + mi * 16 + lrow) * 80 + (k16 + lcol) * 2);
#pragma unroll
            for (int nh = 0; nh < 2; ++nh) {
                uint32_t r[4];
                ldsm4t(r, bh_base + (k16 + lrow) * 272 + (wn * 32 + nh * 16 + lcol) * 2);
                bh[nh * 2][0] = r[0]; bh[nh * 2][1] = r[1];
                bh[nh * 2 + 1][0] = r[2]; bh[nh * 2 + 1][1] = r[3];
            }
#pragma unroll
            for (int mi = 0; mi < 4; ++mi)
#pragma unroll
                for (int ni = 0; ni < 4; ++ni) mma_bf16(acc[mi][ni], af[mi], bh[ni]);

#pragma unroll
            for (int nh = 0; nh < 2; ++nh) {
                uint32_t r[4];
                ldsm4t(r, bl_base + (k16 + lrow) * 272 + (wn * 32 + nh * 16 + lcol) * 2);
                bl[nh * 2][0] = r[0]; bl[nh * 2][1] = r[1];
                bl[nh * 2 + 1][0] = r[2]; bl[nh * 2 + 1][1] = r[3];
            }
#pragma unroll
            for (int mi = 0; mi < 4; ++mi)
#pragma unroll
                for (int ni = 0; ni < 4; ++ni) mma_bf16(acc[mi][ni], af[mi], bl[ni]);

#pragma unroll
            for (int mi = 0; mi < 4; ++mi)
                ldsm4(af[mi], al_base + (wm * 64 + mi * 16 + lrow) * 80 + (k16 + lcol) * 2);
#pragma unroll
            for (int mi = 0; mi < 4; ++mi)
#pragma unroll
                for (int ni = 0; ni < 4; ++ni) mma_bf16(acc[mi][ni], af[mi], bh[ni]);
        }
        __syncthreads();
    }

    // ---- epilogue: store feat (fp16) + fused el/er ----
    const int g = lane >> 2;
    const int t = lane & 3;
    const int h = (bcol >> 5) + wn;

    float a_l[4][2], a_r[4][2];
#pragma unroll
    for (int ni = 0; ni < 4; ++ni) {
        int col = ni * 8 + 2 * t;
        a_l[ni][0] = __ldg(&al[h * 32 + col]);
        a_l[ni][1] = __ldg(&al[h * 32 + col + 1]);
        a_r[ni][0] = __ldg(&ar[h * 32 + col]);
        a_r[ni][1] = __ldg(&ar[h * 32 + col + 1]);
    }

#pragma unroll
    for (int mi = 0; mi < 4; ++mi) {
        int r0 = brow + wm * 64 + mi * 16 + g;
        int r1 = r0 + 8;
        float el0 = 0.f, er0 = 0.f, el1 = 0.f, er1 = 0.f;
#pragma unroll
        for (int ni = 0; ni < 4; ++ni) {
            float d0 = acc[mi][ni][0], d1 = acc[mi][ni][1];
            float d2 = acc[mi][ni][2], d3 = acc[mi][ni][3];
            el0 += d0 * a_l[ni][0] + d1 * a_l[ni][1];
            er0 += d0 * a_r[ni][0] + d1 * a_r[ni][1];
            el1 += d2 * a_l[ni][0] + d3 * a_l[ni][1];
            er1 += d2 * a_r[ni][0] + d3 * a_r[ni][1];
            int cc = bcol + wn * 32 + ni * 8 + 2 * t;
            if (r0 < N_NODES)
                *(__half2*)&g_feat16[(size_t)r0 * 256 + cc] = __floats2half2_rn(d0, d1);
            if (r1 < N_NODES)
                *(__half2*)&g_feat16[(size_t)r1 * 256 + cc] = __floats2half2_rn(d2, d3);
        }
        el0 += __shfl_xor_sync(0xffffffff, el0, 1); el0 += __shfl_xor_sync(0xffffffff, el0, 2);
        er0 += __shfl_xor_sync(0xffffffff, er0, 1); er0 += __shfl_xor_sync(0xffffffff, er0, 2);
        el1 += __shfl_xor_sync(0xffffffff, el1, 1); el1 += __shfl_xor_sync(0xffffffff, el1, 2);
        er1 += __shfl_xor_sync(0xffffffff, er1, 1); er1 += __shfl_xor_sync(0xffffffff, er1, 2);
        if (t == 0) {
            if (r0 < N_NODES) { g_el[r0 * 8 + h] = el0; g_er[r0 * 8 + h] = er0; }
            if (r1 < N_NODES) { g_el[r1 * 8 + h] = el1; g_er[r1 * 8 + h] = er1; }
        }
    }
}

// ---------------- aggregation v11: v9 + per-pair named barrier merge ----------------
// Block = 4 nodes x 2 warps. The two warps of a node merge through SMEM with a
// named barrier over just their 64 threads (bar.sync nl+1, 64) — no cross-node
// straggler coupling, no full-block barrier.
template <int OUT>
__global__ __launch_bounds__(256) void agg_kernel(const float* __restrict__ bias,
                                                  float* __restrict__ out_ext) {
    __shared__ float2 s_acc[4][4][32];
    __shared__ float s_sum[4][8];

    const int wid = threadIdx.x >> 5;
    const int lane = threadIdx.x & 31;
    const int nl = wid >> 1;
    const int half = wid & 1;
    const int node = blockIdx.x * 4 + nl;

    const int beg = g_rowoff[node];
    const int end = g_rowoff[node + 1];
    const int deg = end - beg;
    const int C0 = (((deg + 3) >> 2) + 1) >> 1;
    const int mid = min(beg + C0 * 4, end);
    const int wbeg = half ? mid : beg;
    const int wend = half ? end : mid;

    const int h8 = lane & 7;
    const int e4 = lane >> 3;
    const int myh = lane >> 2;
    const float er_v = g_er[node * 8 + h8];

    float ssum = 0.f;
    float2 acc[4];
#pragma unroll
    for (int c = 0; c < 4; ++c) acc[c] = make_float2(0.f, 0.f);

    const int nfull = wbeg + ((wend - wbeg) & ~3);

    auto do_edge = [&](int s, float w, int e) {
        float wl = __shfl_sync(0xffffffff, w, e * 8 + myh);
        uint4 u = *(const uint4*)&g_feat16[(size_t)s * 256 + lane * 8];
        float2 v0 = __half22float2(*(const __half2*)&u.x);
        float2 v1 = __half22float2(*(const __half2*)&u.y);
        float2 v2 = __half22float2(*(const __half2*)&u.z);
        float2 v3 = __half22float2(*(const __half2*)&u.w);
        acc[0].x = fmaf(wl, v0.x, acc[0].x); acc[0].y = fmaf(wl, v0.y, acc[0].y);
        acc[1].x = fmaf(wl, v1.x, acc[1].x); acc[1].y = fmaf(wl, v1.y, acc[1].y);
        acc[2].x = fmaf(wl, v2.x, acc[2].x); acc[2].y = fmaf(wl, v2.y, acc[2].y);
        acc[3].x = fmaf(wl, v3.x, acc[3].x); acc[3].y = fmaf(wl, v3.y, acc[3].y);
    };

    for (int cs = wbeg; cs < nfull; cs += 4) {
        int s = g_srcs[cs + e4];
        float w = __expf(leaky(g_el[s * 8 + h8] + er_v));
        ssum += w;
#pragma unroll
        for (int e = 0; e < 4; ++e) {
            int se = __shfl_sync(0xffffffff, s, e * 8);
            do_edge(se, w, e);
        }
    }

    if (nfull < wend) {
        const int nn = wend - nfull;
        int s = 0;
        float w = 0.f;
        if (e4 < nn) {
            s = g_srcs[nfull + e4];
            w = __expf(leaky(g_el[s * 8 + h8] + er_v));
        }
        ssum += w;
#pragma unroll
        for (int e = 0; e < 3; ++e) {
            if (e >= nn) break;
            int se = __shfl_sync(0xffffffff, s, e * 8);
            do_edge(se, w, e);
        }
    }

    ssum += __shfl_xor_sync(0xffffffff, ssum, 8);
    ssum += __shfl_xor_sync(0xffffffff, ssum, 16);

    if (half) {
#pragma unroll
        for (int c = 0; c < 4; ++c) s_acc[nl][c][lane] = acc[c];
        if (lane < 8) s_sum[nl][lane] = ssum;
    }
    // per-pair named barrier: only the 2 warps of this node synchronize
    asm volatile("bar.sync %0, 64;" :: "r"(nl + 1) : "memory");
    if (!half) {
        float tot = ssum + s_sum[nl][h8];
        float sden = __shfl_sync(0xffffffff, tot, myh);
        const bool nonempty = (deg > 0);
        const float inv = nonempty ? 1.f / sden : 0.f;
        const int col = myh * 32 + 8 * (lane & 3);
        float o[8];
#pragma unroll
        for (int c = 0; c < 4; ++c) {
            float2 a = s_acc[nl][c][lane];
            o[2 * c]     = fmaxf((acc[c].x + a.x) * inv + __ldg(&bias[col + 2 * c]),     0.f);
            o[2 * c + 1] = fmaxf((acc[c].y + a.y) * inv + __ldg(&bias[col + 2 * c + 1]), 0.f);
        }
        if (OUT == 0) {
#pragma unroll
            for (int c = 0; c < 4; ++c) {
                __nv_bfloat16 hx = __float2bfloat16_rn(o[2 * c]);
                __nv_bfloat16 hy = __float2bfloat16_rn(o[2 * c + 1]);
                *(uint32_t*)&g_Ah[(size_t)node * 256 + col + 2 * c] = pack2(hx, hy);
                *(uint32_t*)&g_Al[(size_t)node * 256 + col + 2 * c] =
                    pack2(__float2bfloat16_rn(o[2 * c] - __bfloat162float(hx)),
                          __float2bfloat16_rn(o[2 * c + 1] - __bfloat162float(hy)));
            }
        } else {
            *(float4*)&out_ext[(size_t)node * 256 + col] =
                make_float4(o[0], o[1], o[2], o[3]);
            *(float4*)&out_ext[(size_t)node * 256 + col + 4] =
                make_float4(o[4], o[5], o[6], o[7]);
        }
    }
}

// ---------------- launch (forked-capture overlap of CSR + W2 prep with layer 1) ----------------
static cudaStream_t g_side = nullptr;
static cudaEvent_t g_evFork = nullptr, g_evJoin = nullptr;
static int g_stream_tried = 0;

extern "C" void kernel_launch(void* const* d_in, const int* in_sizes, int n_in,
                              void* d_out, int out_size) {
    const float* data = (const float*)d_in[0];
    const int*   src  = (const int*)d_in[1];
    const int*   dst  = (const int*)d_in[2];
    const float* W1   = (const float*)d_in[3];
    const float* al1  = (const float*)d_in[4];
    const float* ar1  = (const float*)d_in[5];
    const float* b1   = (const float*)d_in[6];
    const float* W2   = (const float*)d_in[7];
    const float* al2  = (const float*)d_in[8];
    const float* ar2  = (const float*)d_in[9];
    const float* b2   = (const float*)d_in[10];
    float* out = (float*)d_out;

    __nv_bfloat16 *dAh = nullptr, *dAl = nullptr;
    __nv_bfloat16 *dW1h = nullptr, *dW1l = nullptr, *dW2h = nullptr, *dW2l = nullptr;
    cudaGetSymbolAddress((void**)&dAh, g_Ah);
    cudaGetSymbolAddress((void**)&dAl, g_Al);
    cudaGetSymbolAddress((void**)&dW1h, g_W1h);
    cudaGetSymbolAddress((void**)&dW1l, g_W1l);
    cudaGetSymbolAddress((void**)&dW2h, g_W2h);
    cudaGetSymbolAddress((void**)&dW2l, g_W2l);

    cudaFuncSetAttribute(hgemm_kernel, cudaFuncAttributeMaxDynamicSharedMemorySize, GEMM_SMEM);

    if (!g_stream_tried) {
        g_stream_tried = 1;
        if (cudaStreamCreateWithFlags(&g_side, cudaStreamNonBlocking) != cudaSuccess)
            g_side = nullptr;
        if (g_side) {
            if (cudaEventCreateWithFlags(&g_evFork, cudaEventDisableTiming) != cudaSuccess ||
                cudaEventCreateWithFlags(&g_evJoin, cudaEventDisableTiming) != cudaSuccess) {
                g_side = nullptr;
            }
        }
    }

    dim3 ggrid((N_NODES + 127) / 128, 2);
    const int nA4 = N_NODES * HID / 4;
    const int nW4 = HID * HID / 4;
    const int agrid = N_NODES / 4;

    if (g_side) {
        cudaEventRecord(g_evFork, 0);
        cudaStreamWaitEvent(g_side, g_evFork, 0);

        // side: CSR + W2 split (dedicated buffers — no race with gemm1's W1 reads)
        zero_count_kernel<<<(N_NODES + 255) / 256, 256, 0, g_side>>>();
        hist_kernel<<<(N_EDGES + 255) / 256, 256, 0, g_side>>>(dst);
        scan_kernel<<<1, 1024, 0, g_side>>>();
        scatter_kernel<<<(N_EDGES + 255) / 256, 256, 0, g_side>>>(src, dst);
        prep_split_kernel<<<(nW4 + 255) / 256, 256, 0, g_side>>>(W2, dW2h, dW2l, nW4);
        cudaEventRecord(g_evJoin, g_side);

        // main: layer-1 path
        prep_split_kernel<<<(nW4 + 255) / 256, 256>>>(W1, dW1h, dW1l, nW4);
        prep_split_kernel<<<(nA4 + 255) / 256, 256>>>(data, dAh, dAl, nA4);
        hgemm_kernel<<<ggrid, 256, GEMM_SMEM>>>(al1, ar1, dW1h, dW1l);

        cudaStreamWaitEvent(0, g_evJoin, 0);
        agg_kernel<0><<<agrid, 256>>>(b1, nullptr);

        hgemm_kernel<<<ggrid, 256, GEMM_SMEM>>>(al2, ar2, dW2h, dW2l);
        agg_kernel<1><<<agrid, 256>>>(b2, out);
    } else {
        // serial fallback
        zero_count_kernel<<<(N_NODES + 255) / 256, 256>>>();
        hist_kernel<<<(N_EDGES + 255) / 256, 256>>>(dst);
        scan_kernel<<<1, 1024>>>();
        scatter_kernel<<<(N_EDGES + 255) / 256, 256>>>(src, dst);

        prep_split_kernel<<<(nW4 + 255) / 256, 256>>>(W1, dW1h, dW1l, nW4);
        prep_split_kernel<<<(nA4 + 255) / 256, 256>>>(data, dAh, dAl, nA4);
        hgemm_kernel<<<ggrid, 256, GEMM_SMEM>>>(al1, ar1, dW1h, dW1l);
        agg_kernel<0><<<agrid, 256>>>(b1, nullptr);

        prep_split_kernel<<<(nW4 + 255) / 256, 256>>>(W2, dW2h, dW2l, nW4);
        hgemm_kernel<<<ggrid, 256, GEMM_SMEM>>>(al2, ar2, dW2h, dW2l);
        agg_kernel<1><<<agrid, 256>>>(b2, out);
    }
}

// round 16
// speedup vs baseline: 1.1019x; 1.1019x over previous
#include <cuda_runtime.h>
#include <cuda_bf16.h>
#include <cuda_fp16.h>
#include <cstdint>

// ---------------- problem constants ----------------
#define N_NODES 50000
#define N_EDGES 800000
#define HID 256
#define HEADS 8
#define NEG_SLOPE 0.2f

// ---------------- device scratch (static, no allocation) ----------------
__device__ __half g_feat16[(size_t)N_NODES * HID];         // x @ W messages (fp16)
__device__ __nv_bfloat16 g_Ah[(size_t)N_NODES * HID];      // GEMM A operand, bf16 high
__device__ __nv_bfloat16 g_Al[(size_t)N_NODES * HID];      // GEMM A operand, bf16 low
__device__ __nv_bfloat16 g_W1h[HID * HID];
__device__ __nv_bfloat16 g_W1l[HID * HID];
__device__ __nv_bfloat16 g_W2h[HID * HID];
__device__ __nv_bfloat16 g_W2l[HID * HID];
__device__ float g_el[(size_t)N_NODES * HEADS];
__device__ float g_er[(size_t)N_NODES * HEADS];
__device__ int   g_count[N_NODES];
__device__ int   g_rowoff[N_NODES + 1];
__device__ int   g_fill[N_NODES];
__device__ int   g_srcs[N_EDGES];

// ---------------- helpers ----------------
__device__ __forceinline__ uint32_t smem_u32(const void* p) {
    uint32_t a;
    asm("{ .reg .u64 t; cvta.to.shared.u64 t, %1; cvt.u32.u64 %0, t; }" : "=r"(a) : "l"(p));
    return a;
}

__device__ __forceinline__ void ldsm4(uint32_t* r, uint32_t a) {
    asm volatile("ldmatrix.sync.aligned.m8n8.x4.shared.b16 {%0,%1,%2,%3}, [%4];"
                 : "=r"(r[0]), "=r"(r[1]), "=r"(r[2]), "=r"(r[3]) : "r"(a));
}

__device__ __forceinline__ void ldsm4t(uint32_t* r, uint32_t a) {
    asm volatile("ldmatrix.sync.aligned.m8n8.x4.trans.shared.b16 {%0,%1,%2,%3}, [%4];"
                 : "=r"(r[0]), "=r"(r[1]), "=r"(r[2]), "=r"(r[3]) : "r"(a));
}

__device__ __forceinline__ void mma_bf16(float* d, const uint32_t* a, const uint32_t* b) {
    asm volatile("mma.sync.aligned.m16n8k16.row.col.f32.bf16.bf16.f32 "
                 "{%0,%1,%2,%3}, {%4,%5,%6,%7}, {%8,%9}, {%0,%1,%2,%3};"
                 : "+f"(d[0]), "+f"(d[1]), "+f"(d[2]), "+f"(d[3])
                 : "r"(a[0]), "r"(a[1]), "r"(a[2]), "r"(a[3]), "r"(b[0]), "r"(b[1]));
}

__device__ __forceinline__ void cp16(uint32_t dst, const void* src, bool valid) {
    int sz = valid ? 16 : 0;
    asm volatile("cp.async.cg.shared.global [%0], [%1], 16, %2;"
                 :: "r"(dst), "l"(src), "r"(sz) : "memory");
}
#define CP_COMMIT() asm volatile("cp.async.commit_group;" ::: "memory")
#define CP_WAIT1()  asm volatile("cp.async.wait_group 1;" ::: "memory")
#define CP_WAIT0()  asm volatile("cp.async.wait_group 0;" ::: "memory")

__device__ __forceinline__ uint32_t pack2(__nv_bfloat16 a, __nv_bfloat16 b) {
    __nv_bfloat162 t; t.x = a; t.y = b;
    return *reinterpret_cast<uint32_t*>(&t);
}

__device__ __forceinline__ float leaky(float x) { return x > 0.f ? x : NEG_SLOPE * x; }

// ---------------- CSR build ----------------
__global__ void zero_count_kernel() {
    int i = blockIdx.x * blockDim.x + threadIdx.x;
    if (i < N_NODES) g_count[i] = 0;
}

__global__ void hist_kernel(const int* __restrict__ dst) {
    int e = blockIdx.x * blockDim.x + threadIdx.x;
    if (e < N_EDGES) atomicAdd(&g_count[dst[e]], 1);
}

__global__ void scan_kernel() {
    __shared__ int sums[1024];
    const int tid = threadIdx.x;
    const int CH = (N_NODES + 1023) / 1024;
    int start = tid * CH;
    int end = start + CH; if (end > N_NODES) end = N_NODES;
    if (start > N_NODES) start = N_NODES;
    int s = 0;
    for (int i = start; i < end; ++i) s += g_count[i];
    sums[tid] = s;
    __syncthreads();
    for (int off = 1; off < 1024; off <<= 1) {
        int v = (tid >= off) ? sums[tid - off] : 0;
        __syncthreads();
        sums[tid] += v;
        __syncthreads();
    }
    int run = (tid == 0) ? 0 : sums[tid - 1];
    for (int i = start; i < end; ++i) {
        int c = g_count[i];
        g_rowoff[i] = run;
        g_fill[i] = run;
        run += c;
    }
    if (tid == 1023) g_rowoff[N_NODES] = run;
}

__global__ void scatter_kernel(const int* __restrict__ src, const int* __restrict__ dst) {
    int e = blockIdx.x * blockDim.x + threadIdx.x;
    if (e < N_EDGES) {
        int p = atomicAdd(&g_fill[dst[e]], 1);
        g_srcs[p] = src[e];
    }
}

// ---------------- fp32 -> bf16 hi/lo split prepass ----------------
__global__ void prep_split_kernel(const float* __restrict__ in,
                                  __nv_bfloat16* __restrict__ hi,
                                  __nv_bfloat16* __restrict__ lo, int n4) {
    int idx = blockIdx.x * blockDim.x + threadIdx.x;
    if (idx >= n4) return;
    float4 x = ((const float4*)in)[idx];
    __nv_bfloat16 hx = __float2bfloat16_rn(x.x);
    __nv_bfloat16 hy = __float2bfloat16_rn(x.y);
    __nv_bfloat16 hz = __float2bfloat16_rn(x.z);
    __nv_bfloat16 hw = __float2bfloat16_rn(x.w);
    uint2 hp = make_uint2(pack2(hx, hy), pack2(hz, hw));
    uint2 lp = make_uint2(
        pack2(__float2bfloat16_rn(x.x - __bfloat162float(hx)),
              __float2bfloat16_rn(x.y - __bfloat162float(hy))),
        pack2(__float2bfloat16_rn(x.z - __bfloat162float(hz)),
              __float2bfloat16_rn(x.w - __bfloat162float(hw))));
    ((uint2*)hi)[idx] = hp;
    ((uint2*)lo)[idx] = lp;
}

// ---------------- HMMA bf16-split GEMM + fused el/er (cp.async 2-stage) ----------------
#define OFF_AH 0
#define OFF_AL 20480
#define OFF_BH 40960
#define OFF_BL 58368
#define GEMM_SMEM 75776

__global__ __launch_bounds__(256) void hgemm_kernel(const float* __restrict__ al,
                                                    const float* __restrict__ ar,
                                                    const __nv_bfloat16* __restrict__ Wh,
                                                    const __nv_bfloat16* __restrict__ Wl) {
    extern __shared__ char sm[];
    const uint32_t sb = smem_u32(sm);

    const int tid = threadIdx.x;
    const int wid = tid >> 5;
    const int lane = tid & 31;
    const int wm = wid >> 2;
    const int wn = wid & 3;
    const int brow = blockIdx.x * 128;
    const int bcol = blockIdx.y * 128;

    float acc[4][4][4];
#pragma unroll
    for (int i = 0; i < 4; ++i)
#pragma unroll
        for (int j = 0; j < 4; ++j)
#pragma unroll
            for (int k = 0; k < 4; ++k) acc[i][j][k] = 0.f;

    const int arow = tid >> 1;
    const int acol = (tid & 1) * 16;
    const int brw = tid >> 3;
    const int bcl = (tid & 7) * 16;

    const bool arow_ok = (brow + arow) < N_NODES;
    const size_t abase = (size_t)(brow + arow) * 256 + acol;

    const int lrow = lane & 15;
    const int lcol = (lane >> 4) << 3;

    auto issue = [&](int c, int st) {
        const int k0 = c * 32;
        uint32_t adst = sb + OFF_AH + st * 10240 + arow * 80 + acol * 2;
        cp16(adst,      &g_Ah[abase + k0],     arow_ok);
        cp16(adst + 16, &g_Ah[abase + k0 + 8], arow_ok);
        uint32_t aldst = sb + OFF_AL + st * 10240 + arow * 80 + acol * 2;
        cp16(aldst,      &g_Al[abase + k0],     arow_ok);
        cp16(aldst + 16, &g_Al[abase + k0 + 8], arow_ok);
        const size_t bbase = (size_t)(k0 + brw) * 256 + bcol + bcl;
        uint32_t bdst = sb + OFF_BH + st * 8704 + brw * 272 + bcl * 2;
        cp16(bdst,      &Wh[bbase],     true);
        cp16(bdst + 16, &Wh[bbase + 8], true);
        uint32_t bldst = sb + OFF_BL + st * 8704 + brw * 272 + bcl * 2;
        cp16(bldst,      &Wl[bbase],     true);
        cp16(bldst + 16, &Wl[bbase + 8], true);
    };

    issue(0, 0);
    CP_COMMIT();

    for (int c = 0; c < 8; ++c) {
        const int st = c & 1;
        if (c < 7) {
            issue(c + 1, st ^ 1);
            CP_COMMIT();
            CP_WAIT1();
        } else {
            CP_WAIT0();
        }
        __syncthreads();

        const uint32_t ah_base = sb + OFF_AH + st * 10240;
        const uint32_t al_base = sb + OFF_AL + st * 10240;
        const uint32_t bh_base = sb + OFF_BH + st * 8704;
        const uint32_t bl_base = sb + OFF_BL + st * 8704;

#pragma unroll
        for (int kk = 0; kk < 2; ++kk) {
            const int k16 = kk * 16;
            uint32_t af[4][4], bh[4][2], bl[4][2];
#pragma unroll
            for (int mi = 0; mi < 4; ++mi)
                ldsm4(af[mi], ah_base + (wm * 64 + mi * 16 + lrow) * 80 + (k16 + lcol) * 2);
#pragma unroll
            for (int nh = 0; nh < 2; ++nh) {
                uint32_t r[4];
                ldsm4t(r, bh_base + (k16 + lrow) * 272 + (wn * 32 + nh * 16 + lcol) * 2);
                bh[nh * 2][0] = r[0]; bh[nh * 2][1] = r[1];
                bh[nh * 2 + 1][0] = r[2]; bh[nh * 2 + 1][1] = r[3];
            }
#pragma unroll
            for (int mi = 0; mi < 4; ++mi)
#pragma unroll
                for (int ni = 0; ni < 4; ++ni) mma_bf16(acc[mi][ni], af[mi], bh[ni]);

#pragma unroll
            for (int nh = 0; nh < 2; ++nh) {
                uint32_t r[4];
                ldsm4t(r, bl_base + (k16 + lrow) * 272 + (wn * 32 + nh * 16 + lcol) * 2);
                bl[nh * 2][0] = r[0]; bl[nh * 2][1] = r[1];
                bl[nh * 2 + 1][0] = r[2]; bl[nh * 2 + 1][1] = r[3];
            }
#pragma unroll
            for (int mi = 0; mi < 4; ++mi)
#pragma unroll
                for (int ni = 0; ni < 4; ++ni) mma_bf16(acc[mi][ni], af[mi], bl[ni]);

#pragma unroll
            for (int mi = 0; mi < 4; ++mi)
                ldsm4(af[mi], al_base + (wm * 64 + mi * 16 + lrow) * 80 + (k16 + lcol) * 2);
#pragma unroll
            for (int mi = 0; mi < 4; ++mi)
#pragma unroll
                for (int ni = 0; ni < 4; ++ni) mma_bf16(acc[mi][ni], af[mi], bh[ni]);
        }
        __syncthreads();
    }

    // ---- epilogue: store feat (fp16) + fused el/er ----
    const int g = lane >> 2;
    const int t = lane & 3;
    const int h = (bcol >> 5) + wn;

    float a_l[4][2], a_r[4][2];
#pragma unroll
    for (int ni = 0; ni < 4; ++ni) {
        int col = ni * 8 + 2 * t;
        a_l[ni][0] = __ldg(&al[h * 32 + col]);
        a_l[ni][1] = __ldg(&al[h * 32 + col + 1]);
        a_r[ni][0] = __ldg(&ar[h * 32 + col]);
        a_r[ni][1] = __ldg(&ar[h * 32 + col + 1]);
    }

#pragma unroll
    for (int mi = 0; mi < 4; ++mi) {
        int r0 = brow + wm * 64 + mi * 16 + g;
        int r1 = r0 + 8;
        float el0 = 0.f, er0 = 0.f, el1 = 0.f, er1 = 0.f;
#pragma unroll
        for (int ni = 0; ni < 4; ++ni) {
            float d0 = acc[mi][ni][0], d1 = acc[mi][ni][1];
            float d2 = acc[mi][ni][2], d3 = acc[mi][ni][3];
            el0 += d0 * a_l[ni][0] + d1 * a_l[ni][1];
            er0 += d0 * a_r[ni][0] + d1 * a_r[ni][1];
            el1 += d2 * a_l[ni][0] + d3 * a_l[ni][1];
            er1 += d2 * a_r[ni][0] + d3 * a_r[ni][1];
            int cc = bcol + wn * 32 + ni * 8 + 2 * t;
            if (r0 < N_NODES)
                *(__half2*)&g_feat16[(size_t)r0 * 256 + cc] = __floats2half2_rn(d0, d1);
            if (r1 < N_NODES)
                *(__half2*)&g_feat16[(size_t)r1 * 256 + cc] = __floats2half2_rn(d2, d3);
        }
        el0 += __shfl_xor_sync(0xffffffff, el0, 1); el0 += __shfl_xor_sync(0xffffffff, el0, 2);
        er0 += __shfl_xor_sync(0xffffffff, er0, 1); er0 += __shfl_xor_sync(0xffffffff, er0, 2);
        el1 += __shfl_xor_sync(0xffffffff, el1, 1); el1 += __shfl_xor_sync(0xffffffff, el1, 2);
        er1 += __shfl_xor_sync(0xffffffff, er1, 1); er1 += __shfl_xor_sync(0xffffffff, er1, 2);
        if (t == 0) {
            if (r0 < N_NODES) { g_el[r0 * 8 + h] = el0; g_er[r0 * 8 + h] = er0; }
            if (r1 < N_NODES) { g_el[r1 * 8 + h] = el1; g_er[r1 * 8 + h] = er1; }
        }
    }
}

// ---------------- aggregation v12: v9 + 8-edge unrolled main loop ----------------
// Full groups of 8 edges: both el gathers issued back-to-back (MLP=2 on the
// critical chain), 8 independent uint4 feat loads per group. Tail uses the
// proven 4-chunk + remainder path unchanged. Merge via __syncthreads.
template <int OUT>
__global__ __launch_bounds__(256) void agg_kernel(const float* __restrict__ bias,
                                                  float* __restrict__ out_ext) {
    __shared__ float2 s_acc[4][4][32];
    __shared__ float s_sum[4][8];

    const int wid = threadIdx.x >> 5;
    const int lane = threadIdx.x & 31;
    const int nl = wid >> 1;
    const int half = wid & 1;
    const int node = blockIdx.x * 4 + nl;

    const int beg = g_rowoff[node];
    const int end = g_rowoff[node + 1];
    const int deg = end - beg;
    const int C0 = (((deg + 3) >> 2) + 1) >> 1;
    const int mid = min(beg + C0 * 4, end);
    const int wbeg = half ? mid : beg;
    const int wend = half ? end : mid;

    const int h8 = lane & 7;
    const int e4 = lane >> 3;
    const int myh = lane >> 2;
    const float er_v = g_er[node * 8 + h8];

    float ssum = 0.f;
    float2 acc[4];
#pragma unroll
    for (int c = 0; c < 4; ++c) acc[c] = make_float2(0.f, 0.f);

    auto do_edge = [&](int s, float w, int e) {
        float wl = __shfl_sync(0xffffffff, w, e * 8 + myh);
        uint4 u = *(const uint4*)&g_feat16[(size_t)s * 256 + lane * 8];
        float2 v0 = __half22float2(*(const __half2*)&u.x);
        float2 v1 = __half22float2(*(const __half2*)&u.y);
        float2 v2 = __half22float2(*(const __half2*)&u.z);
        float2 v3 = __half22float2(*(const __half2*)&u.w);
        acc[0].x = fmaf(wl, v0.x, acc[0].x); acc[0].y = fmaf(wl, v0.y, acc[0].y);
        acc[1].x = fmaf(wl, v1.x, acc[1].x); acc[1].y = fmaf(wl, v1.y, acc[1].y);
        acc[2].x = fmaf(wl, v2.x, acc[2].x); acc[2].y = fmaf(wl, v2.y, acc[2].y);
        acc[3].x = fmaf(wl, v3.x, acc[3].x); acc[3].y = fmaf(wl, v3.y, acc[3].y);
    };

    int cs = wbeg;

    // ---- full groups of 8 edges (branch-free, dual el gather) ----
    for (; cs + 8 <= wend; cs += 8) {
        int sA = g_srcs[cs + e4];
        int sB = g_srcs[cs + 4 + e4];
        float wA = __expf(leaky(g_el[sA * 8 + h8] + er_v));
        float wB = __expf(leaky(g_el[sB * 8 + h8] + er_v));
        ssum += wA + wB;
#pragma unroll
        for (int e = 0; e < 4; ++e) {
            int se = __shfl_sync(0xffffffff, sA, e * 8);
            do_edge(se, wA, e);
        }
#pragma unroll
        for (int e = 0; e < 4; ++e) {
            int se = __shfl_sync(0xffffffff, sB, e * 8);
            do_edge(se, wB, e);
        }
    }

    // ---- full chunk of 4 (at most one) ----
    if (cs + 4 <= wend) {
        int s = g_srcs[cs + e4];
        float w = __expf(leaky(g_el[s * 8 + h8] + er_v));
        ssum += w;
#pragma unroll
        for (int e = 0; e < 4; ++e) {
            int se = __shfl_sync(0xffffffff, s, e * 8);
            do_edge(se, w, e);
        }
        cs += 4;
    }

    // ---- remainder (0-3 edges) ----
    if (cs < wend) {
        const int nn = wend - cs;
        int s = 0;
        float w = 0.f;
        if (e4 < nn) {
            s = g_srcs[cs + e4];
            w = __expf(leaky(g_el[s * 8 + h8] + er_v));
        }
        ssum += w;
#pragma unroll
        for (int e = 0; e < 3; ++e) {
            if (e >= nn) break;
            int se = __shfl_sync(0xffffffff, s, e * 8);
            do_edge(se, w, e);
        }
    }

    ssum += __shfl_xor_sync(0xffffffff, ssum, 8);
    ssum += __shfl_xor_sync(0xffffffff, ssum, 16);

    if (half) {
#pragma unroll
        for (int c = 0; c < 4; ++c) s_acc[nl][c][lane] = acc[c];
        if (lane < 8) s_sum[nl][lane] = ssum;
    }
    __syncthreads();
    if (!half) {
        float tot = ssum + s_sum[nl][h8];
        float sden = __shfl_sync(0xffffffff, tot, myh);
        const bool nonempty = (deg > 0);
        const float inv = nonempty ? 1.f / sden : 0.f;
        const int col = myh * 32 + 8 * (lane & 3);
        float o[8];
#pragma unroll
        for (int c = 0; c < 4; ++c) {
            float2 a = s_acc[nl][c][lane];
            o[2 * c]     = fmaxf((acc[c].x + a.x) * inv + __ldg(&bias[col + 2 * c]),     0.f);
            o[2 * c + 1] = fmaxf((acc[c].y + a.y) * inv + __ldg(&bias[col + 2 * c + 1]), 0.f);
        }
        if (OUT == 0) {
#pragma unroll
            for (int c = 0; c < 4; ++c) {
                __nv_bfloat16 hx = __float2bfloat16_rn(o[2 * c]);
                __nv_bfloat16 hy = __float2bfloat16_rn(o[2 * c + 1]);
                *(uint32_t*)&g_Ah[(size_t)node * 256 + col + 2 * c] = pack2(hx, hy);
                *(uint32_t*)&g_Al[(size_t)node * 256 + col + 2 * c] =
                    pack2(__float2bfloat16_rn(o[2 * c] - __bfloat162float(hx)),
                          __float2bfloat16_rn(o[2 * c + 1] - __bfloat162float(hy)));
            }
        } else {
            *(float4*)&out_ext[(size_t)node * 256 + col] =
                make_float4(o[0], o[1], o[2], o[3]);
            *(float4*)&out_ext[(size_t)node * 256 + col + 4] =
                make_float4(o[4], o[5], o[6], o[7]);
        }
    }
}

// ---------------- launch (forked-capture overlap of CSR + W2 prep with layer 1) ----------------
static cudaStream_t g_side = nullptr;
static cudaEvent_t g_evFork = nullptr, g_evJoin = nullptr;
static int g_stream_tried = 0;

extern "C" void kernel_launch(void* const* d_in, const int* in_sizes, int n_in,
                              void* d_out, int out_size) {
    const float* data = (const float*)d_in[0];
    const int*   src  = (const int*)d_in[1];
    const int*   dst  = (const int*)d_in[2];
    const float* W1   = (const float*)d_in[3];
    const float* al1  = (const float*)d_in[4];
    const float* ar1  = (const float*)d_in[5];
    const float* b1   = (const float*)d_in[6];
    const float* W2   = (const float*)d_in[7];
    const float* al2  = (const float*)d_in[8];
    const float* ar2  = (const float*)d_in[9];
    const float* b2   = (const float*)d_in[10];
    float* out = (float*)d_out;

    __nv_bfloat16 *dAh = nullptr, *dAl = nullptr;
    __nv_bfloat16 *dW1h = nullptr, *dW1l = nullptr, *dW2h = nullptr, *dW2l = nullptr;
    cudaGetSymbolAddress((void**)&dAh, g_Ah);
    cudaGetSymbolAddress((void**)&dAl, g_Al);
    cudaGetSymbolAddress((void**)&dW1h, g_W1h);
    cudaGetSymbolAddress((void**)&dW1l, g_W1l);
    cudaGetSymbolAddress((void**)&dW2h, g_W2h);
    cudaGetSymbolAddress((void**)&dW2l, g_W2l);

    cudaFuncSetAttribute(hgemm_kernel, cudaFuncAttributeMaxDynamicSharedMemorySize, GEMM_SMEM);

    if (!g_stream_tried) {
        g_stream_tried = 1;
        if (cudaStreamCreateWithFlags(&g_side, cudaStreamNonBlocking) != cudaSuccess)
            g_side = nullptr;
        if (g_side) {
            if (cudaEventCreateWithFlags(&g_evFork, cudaEventDisableTiming) != cudaSuccess ||
                cudaEventCreateWithFlags(&g_evJoin, cudaEventDisableTiming) != cudaSuccess) {
                g_side = nullptr;
            }
        }
    }

    dim3 ggrid((N_NODES + 127) / 128, 2);
    const int nA4 = N_NODES * HID / 4;
    const int nW4 = HID * HID / 4;
    const int agrid = N_NODES / 4;

    if (g_side) {
        cudaEventRecord(g_evFork, 0);
        cudaStreamWaitEvent(g_side, g_evFork, 0);

        // side: CSR + W2 split (dedicated buffers — no race with gemm1's W1 reads)
        zero_count_kernel<<<(N_NODES + 255) / 256, 256, 0, g_side>>>();
        hist_kernel<<<(N_EDGES + 255) / 256, 256, 0, g_side>>>(dst);
        scan_kernel<<<1, 1024, 0, g_side>>>();
        scatter_kernel<<<(N_EDGES + 255) / 256, 256, 0, g_side>>>(src, dst);
        prep_split_kernel<<<(nW4 + 255) / 256, 256, 0, g_side>>>(W2, dW2h, dW2l, nW4);
        cudaEventRecord(g_evJoin, g_side);

        // main: layer-1 path
        prep_split_kernel<<<(nW4 + 255) / 256, 256>>>(W1, dW1h, dW1l, nW4);
        prep_split_kernel<<<(nA4 + 255) / 256, 256>>>(data, dAh, dAl, nA4);
        hgemm_kernel<<<ggrid, 256, GEMM_SMEM>>>(al1, ar1, dW1h, dW1l);

        cudaStreamWaitEvent(0, g_evJoin, 0);
        agg_kernel<0><<<agrid, 256>>>(b1, nullptr);

        hgemm_kernel<<<ggrid, 256, GEMM_SMEM>>>(al2, ar2, dW2h, dW2l);
        agg_kernel<1><<<agrid, 256>>>(b2, out);
    } else {
        // serial fallback
        zero_count_kernel<<<(N_NODES + 255) / 256, 256>>>();
        hist_kernel<<<(N_EDGES + 255) / 256, 256>>>(dst);
        scan_kernel<<<1, 1024>>>();
        scatter_kernel<<<(N_EDGES + 255) / 256, 256>>>(src, dst);

        prep_split_kernel<<<(nW4 + 255) / 256, 256>>>(W1, dW1h, dW1l, nW4);
        prep_split_kernel<<<(nA4 + 255) / 256, 256>>>(data, dAh, dAl, nA4);
        hgemm_kernel<<<ggrid, 256, GEMM_SMEM>>>(al1, ar1, dW1h, dW1l);
        agg_kernel<0><<<agrid, 256>>>(b1, nullptr);

        prep_split_kernel<<<(nW4 + 255) / 256, 256>>>(W2, dW2h, dW2l, nW4);
        hgemm_kernel<<<ggrid, 256, GEMM_SMEM>>>(al2, ar2, dW2h, dW2l);
        agg_kernel<1><<<agrid, 256>>>(b2, out);
    }
}

// round 17
// speedup vs baseline: 1.3114x; 1.1902x over previous
#include <cuda_runtime.h>
#include <cuda_bf16.h>
#include <cuda_fp16.h>
#include <cstdint>

// ---------------- problem constants ----------------
#define N_NODES 50000
#define N_EDGES 800000
#define HID 256
#define HEADS 8
#define NEG_SLOPE 0.2f

// ---------------- device scratch (static, no allocation) ----------------
__device__ __half g_feat16[(size_t)N_NODES * HID];   // x @ W messages (fp16)
__device__ __half g_A16[(size_t)N_NODES * HID];      // GEMM A operand (fp16)
__device__ __half g_W1_16[HID * HID];
__device__ __half g_W2_16[HID * HID];
__device__ float g_el[(size_t)N_NODES * HEADS];
__device__ float g_er[(size_t)N_NODES * HEADS];
__device__ int   g_count[N_NODES];
__device__ int   g_rowoff[N_NODES + 1];
__device__ int   g_fill[N_NODES];
__device__ int   g_srcs[N_EDGES];

// ---------------- helpers ----------------
__device__ __forceinline__ uint32_t smem_u32(const void* p) {
    uint32_t a;
    asm("{ .reg .u64 t; cvta.to.shared.u64 t, %1; cvt.u32.u64 %0, t; }" : "=r"(a) : "l"(p));
    return a;
}

__device__ __forceinline__ void ldsm4(uint32_t* r, uint32_t a) {
    asm volatile("ldmatrix.sync.aligned.m8n8.x4.shared.b16 {%0,%1,%2,%3}, [%4];"
                 : "=r"(r[0]), "=r"(r[1]), "=r"(r[2]), "=r"(r[3]) : "r"(a));
}

__device__ __forceinline__ void ldsm4t(uint32_t* r, uint32_t a) {
    asm volatile("ldmatrix.sync.aligned.m8n8.x4.trans.shared.b16 {%0,%1,%2,%3}, [%4];"
                 : "=r"(r[0]), "=r"(r[1]), "=r"(r[2]), "=r"(r[3]) : "r"(a));
}

__device__ __forceinline__ void mma_fp16(float* d, const uint32_t* a, const uint32_t* b) {
    asm volatile("mma.sync.aligned.m16n8k16.row.col.f32.f16.f16.f32 "
                 "{%0,%1,%2,%3}, {%4,%5,%6,%7}, {%8,%9}, {%0,%1,%2,%3};"
                 : "+f"(d[0]), "+f"(d[1]), "+f"(d[2]), "+f"(d[3])
                 : "r"(a[0]), "r"(a[1]), "r"(a[2]), "r"(a[3]), "r"(b[0]), "r"(b[1]));
}

__device__ __forceinline__ void cp16(uint32_t dst, const void* src, bool valid) {
    int sz = valid ? 16 : 0;
    asm volatile("cp.async.cg.shared.global [%0], [%1], 16, %2;"
                 :: "r"(dst), "l"(src), "r"(sz) : "memory");
}
#define CP_COMMIT() asm volatile("cp.async.commit_group;" ::: "memory")
#define CP_WAIT1()  asm volatile("cp.async.wait_group 1;" ::: "memory")
#define CP_WAIT0()  asm volatile("cp.async.wait_group 0;" ::: "memory")

__device__ __forceinline__ float leaky(float x) { return x > 0.f ? x : NEG_SLOPE * x; }

// ---------------- CSR build ----------------
__global__ void zero_count_kernel() {
    int i = blockIdx.x * blockDim.x + threadIdx.x;
    if (i < N_NODES) g_count[i] = 0;
}

__global__ void hist_kernel(const int* __restrict__ dst) {
    int e = blockIdx.x * blockDim.x + threadIdx.x;
    if (e < N_EDGES) atomicAdd(&g_count[dst[e]], 1);
}

__global__ void scan_kernel() {
    __shared__ int sums[1024];
    const int tid = threadIdx.x;
    const int CH = (N_NODES + 1023) / 1024;
    int start = tid * CH;
    int end = start + CH; if (end > N_NODES) end = N_NODES;
    if (start > N_NODES) start = N_NODES;
    int s = 0;
    for (int i = start; i < end; ++i) s += g_count[i];
    sums[tid] = s;
    __syncthreads();
    for (int off = 1; off < 1024; off <<= 1) {
        int v = (tid >= off) ? sums[tid - off] : 0;
        __syncthreads();
        sums[tid] += v;
        __syncthreads();
    }
    int run = (tid == 0) ? 0 : sums[tid - 1];
    for (int i = start; i < end; ++i) {
        int c = g_count[i];
        g_rowoff[i] = run;
        g_fill[i] = run;
        run += c;
    }
    if (tid == 1023) g_rowoff[N_NODES] = run;
}

__global__ void scatter_kernel(const int* __restrict__ src, const int* __restrict__ dst) {
    int e = blockIdx.x * blockDim.x + threadIdx.x;
    if (e < N_EDGES) {
        int p = atomicAdd(&g_fill[dst[e]], 1);
        g_srcs[p] = src[e];
    }
}

// ---------------- fp32 -> fp16 convert prepass ----------------
__global__ void prep_half_kernel(const float* __restrict__ in,
                                 __half* __restrict__ out, int n4) {
    int idx = blockIdx.x * blockDim.x + threadIdx.x;
    if (idx >= n4) return;
    float4 x = ((const float4*)in)[idx];
    __half2 h0 = __floats2half2_rn(x.x, x.y);
    __half2 h1 = __floats2half2_rn(x.z, x.w);
    uint2 p;
    p.x = *reinterpret_cast<uint32_t*>(&h0);
    p.y = *reinterpret_cast<uint32_t*>(&h1);
    ((uint2*)out)[idx] = p;
}

// ---------------- fp16 HMMA GEMM + fused el/er (cp.async 2-stage) ----------------
// SMEM: A 2 stages x 128 rows x 80B @0 (stride 10240); B 2 stages x 32 rows x 272B @20480 (stride 8704)
#define OFF_A 0
#define OFF_B 20480
#define GEMM_SMEM 37888

__global__ __launch_bounds__(256) void hgemm_kernel(const float* __restrict__ al,
                                                    const float* __restrict__ ar,
                                                    const __half* __restrict__ W16) {
    extern __shared__ char sm[];
    const uint32_t sb = smem_u32(sm);

    const int tid = threadIdx.x;
    const int wid = tid >> 5;
    const int lane = tid & 31;
    const int wm = wid >> 2;
    const int wn = wid & 3;
    const int brow = blockIdx.x * 128;
    const int bcol = blockIdx.y * 128;

    float acc[4][4][4];
#pragma unroll
    for (int i = 0; i < 4; ++i)
#pragma unroll
        for (int j = 0; j < 4; ++j)
#pragma unroll
            for (int k = 0; k < 4; ++k) acc[i][j][k] = 0.f;

    const int arow = tid >> 1;            // 0..127
    const int acol = (tid & 1) * 16;      // elements
    const int brw = tid >> 3;             // 0..31
    const int bcl = (tid & 7) * 16;       // elements

    const bool arow_ok = (brow + arow) < N_NODES;
    const size_t abase = (size_t)(brow + arow) * 256 + acol;

    const int lrow = lane & 15;
    const int lcol = (lane >> 4) << 3;

    auto issue = [&](int c, int st) {
        const int k0 = c * 32;
        uint32_t adst = sb + OFF_A + st * 10240 + arow * 80 + acol * 2;
        cp16(adst,      &g_A16[abase + k0],     arow_ok);
        cp16(adst + 16, &g_A16[abase + k0 + 8], arow_ok);
        const size_t bbase = (size_t)(k0 + brw) * 256 + bcol + bcl;
        uint32_t bdst = sb + OFF_B + st * 8704 + brw * 272 + bcl * 2;
        cp16(bdst,      &W16[bbase],     true);
        cp16(bdst + 16, &W16[bbase + 8], true);
    };

    issue(0, 0);
    CP_COMMIT();

    for (int c = 0; c < 8; ++c) {
        const int st = c & 1;
        if (c < 7) {
            issue(c + 1, st ^ 1);
            CP_COMMIT();
            CP_WAIT1();
        } else {
            CP_WAIT0();
        }
        __syncthreads();

        const uint32_t a_base = sb + OFF_A + st * 10240;
        const uint32_t b_base = sb + OFF_B + st * 8704;

#pragma unroll
        for (int kk = 0; kk < 2; ++kk) {
            const int k16 = kk * 16;
            uint32_t af[4][4], bf[4][2];
#pragma unroll
            for (int mi = 0; mi < 4; ++mi)
                ldsm4(af[mi], a_base + (wm * 64 + mi * 16 + lrow) * 80 + (k16 + lcol) * 2);
#pragma unroll
            for (int nh = 0; nh < 2; ++nh) {
                uint32_t r[4];
                ldsm4t(r, b_base + (k16 + lrow) * 272 + (wn * 32 + nh * 16 + lcol) * 2);
                bf[nh * 2][0] = r[0]; bf[nh * 2][1] = r[1];
                bf[nh * 2 + 1][0] = r[2]; bf[nh * 2 + 1][1] = r[3];
            }
#pragma unroll
            for (int mi = 0; mi < 4; ++mi)
#pragma unroll
                for (int ni = 0; ni < 4; ++ni) mma_fp16(acc[mi][ni], af[mi], bf[ni]);
        }
        __syncthreads();
    }

    // ---- epilogue: store feat (fp16) + fused el/er ----
    const int g = lane >> 2;
    const int t = lane & 3;
    const int h = (bcol >> 5) + wn;

    float a_l[4][2], a_r[4][2];
#pragma unroll
    for (int ni = 0; ni < 4; ++ni) {
        int col = ni * 8 + 2 * t;
        a_l[ni][0] = __ldg(&al[h * 32 + col]);
        a_l[ni][1] = __ldg(&al[h * 32 + col + 1]);
        a_r[ni][0] = __ldg(&ar[h * 32 + col]);
        a_r[ni][1] = __ldg(&ar[h * 32 + col + 1]);
    }

#pragma unroll
    for (int mi = 0; mi < 4; ++mi) {
        int r0 = brow + wm * 64 + mi * 16 + g;
        int r1 = r0 + 8;
        float el0 = 0.f, er0 = 0.f, el1 = 0.f, er1 = 0.f;
#pragma unroll
        for (int ni = 0; ni < 4; ++ni) {
            float d0 = acc[mi][ni][0], d1 = acc[mi][ni][1];
            float d2 = acc[mi][ni][2], d3 = acc[mi][ni][3];
            el0 += d0 * a_l[ni][0] + d1 * a_l[ni][1];
            er0 += d0 * a_r[ni][0] + d1 * a_r[ni][1];
            el1 += d2 * a_l[ni][0] + d3 * a_l[ni][1];
            er1 += d2 * a_r[ni][0] + d3 * a_r[ni][1];
            int cc = bcol + wn * 32 + ni * 8 + 2 * t;
            if (r0 < N_NODES)
                *(__half2*)&g_feat16[(size_t)r0 * 256 + cc] = __floats2half2_rn(d0, d1);
            if (r1 < N_NODES)
                *(__half2*)&g_feat16[(size_t)r1 * 256 + cc] = __floats2half2_rn(d2, d3);
        }
        el0 += __shfl_xor_sync(0xffffffff, el0, 1); el0 += __shfl_xor_sync(0xffffffff, el0, 2);
        er0 += __shfl_xor_sync(0xffffffff, er0, 1); er0 += __shfl_xor_sync(0xffffffff, er0, 2);
        el1 += __shfl_xor_sync(0xffffffff, el1, 1); el1 += __shfl_xor_sync(0xffffffff, el1, 2);
        er1 += __shfl_xor_sync(0xffffffff, er1, 1); er1 += __shfl_xor_sync(0xffffffff, er1, 2);
        if (t == 0) {
            if (r0 < N_NODES) { g_el[r0 * 8 + h] = el0; g_er[r0 * 8 + h] = er0; }
            if (r1 < N_NODES) { g_el[r1 * 8 + h] = el1; g_er[r1 * 8 + h] = er1; }
        }
    }
}

// ---------------- aggregation v9: uint4 feat loads, 2 warps/node ----------------
template <int OUT>
__global__ __launch_bounds__(256) void agg_kernel(const float* __restrict__ bias,
                                                  float* __restrict__ out_ext) {
    __shared__ float2 s_acc[4][4][32];
    __shared__ float s_sum[4][8];

    const int wid = threadIdx.x >> 5;
    const int lane = threadIdx.x & 31;
    const int nl = wid >> 1;
    const int half = wid & 1;
    const int node = blockIdx.x * 4 + nl;

    const int beg = g_rowoff[node];
    const int end = g_rowoff[node + 1];
    const int deg = end - beg;
    const int C0 = (((deg + 3) >> 2) + 1) >> 1;
    const int mid = min(beg + C0 * 4, end);
    const int wbeg = half ? mid : beg;
    const int wend = half ? end : mid;

    const int h8 = lane & 7;
    const int e4 = lane >> 3;
    const int myh = lane >> 2;
    const float er_v = g_er[node * 8 + h8];

    float ssum = 0.f;
    float2 acc[4];
#pragma unroll
    for (int c = 0; c < 4; ++c) acc[c] = make_float2(0.f, 0.f);

    const int nfull = wbeg + ((wend - wbeg) & ~3);

    auto do_edge = [&](int s, float w, int e) {
        float wl = __shfl_sync(0xffffffff, w, e * 8 + myh);
        uint4 u = *(const uint4*)&g_feat16[(size_t)s * 256 + lane * 8];
        float2 v0 = __half22float2(*(const __half2*)&u.x);
        float2 v1 = __half22float2(*(const __half2*)&u.y);
        float2 v2 = __half22float2(*(const __half2*)&u.z);
        float2 v3 = __half22float2(*(const __half2*)&u.w);
        acc[0].x = fmaf(wl, v0.x, acc[0].x); acc[0].y = fmaf(wl, v0.y, acc[0].y);
        acc[1].x = fmaf(wl, v1.x, acc[1].x); acc[1].y = fmaf(wl, v1.y, acc[1].y);
        acc[2].x = fmaf(wl, v2.x, acc[2].x); acc[2].y = fmaf(wl, v2.y, acc[2].y);
        acc[3].x = fmaf(wl, v3.x, acc[3].x); acc[3].y = fmaf(wl, v3.y, acc[3].y);
    };

    for (int cs = wbeg; cs < nfull; cs += 4) {
        int s = g_srcs[cs + e4];
        float w = __expf(leaky(g_el[s * 8 + h8] + er_v));
        ssum += w;
#pragma unroll
        for (int e = 0; e < 4; ++e) {
            int se = __shfl_sync(0xffffffff, s, e * 8);
            do_edge(se, w, e);
        }
    }

    if (nfull < wend) {
        const int nn = wend - nfull;
        int s = 0;
        float w = 0.f;
        if (e4 < nn) {
            s = g_srcs[nfull + e4];
            w = __expf(leaky(g_el[s * 8 + h8] + er_v));
        }
        ssum += w;
#pragma unroll
        for (int e = 0; e < 3; ++e) {
            if (e >= nn) break;
            int se = __shfl_sync(0xffffffff, s, e * 8);
            do_edge(se, w, e);
        }
    }

    ssum += __shfl_xor_sync(0xffffffff, ssum, 8);
    ssum += __shfl_xor_sync(0xffffffff, ssum, 16);

    if (half) {
#pragma unroll
        for (int c = 0; c < 4; ++c) s_acc[nl][c][lane] = acc[c];
        if (lane < 8) s_sum[nl][lane] = ssum;
    }
    __syncthreads();
    if (!half) {
        float tot = ssum + s_sum[nl][h8];
        float sden = __shfl_sync(0xffffffff, tot, myh);
        const bool nonempty = (deg > 0);
        const float inv = nonempty ? 1.f / sden : 0.f;
        const int col = myh * 32 + 8 * (lane & 3);
        float o[8];
#pragma unroll
        for (int c = 0; c < 4; ++c) {
            float2 a = s_acc[nl][c][lane];
            o[2 * c]     = fmaxf((acc[c].x + a.x) * inv + __ldg(&bias[col + 2 * c]),     0.f);
            o[2 * c + 1] = fmaxf((acc[c].y + a.y) * inv + __ldg(&bias[col + 2 * c + 1]), 0.f);
        }
        if (OUT == 0) {
            // write fp16 GEMM A operand for layer 2 (single uint4 = 8 halves)
            __half2 h0 = __floats2half2_rn(o[0], o[1]);
            __half2 h1 = __floats2half2_rn(o[2], o[3]);
            __half2 h2 = __floats2half2_rn(o[4], o[5]);
            __half2 h3 = __floats2half2_rn(o[6], o[7]);
            uint4 p;
            p.x = *reinterpret_cast<uint32_t*>(&h0);
            p.y = *reinterpret_cast<uint32_t*>(&h1);
            p.z = *reinterpret_cast<uint32_t*>(&h2);
            p.w = *reinterpret_cast<uint32_t*>(&h3);
            *(uint4*)&g_A16[(size_t)node * 256 + col] = p;
        } else {
            *(float4*)&out_ext[(size_t)node * 256 + col] =
                make_float4(o[0], o[1], o[2], o[3]);
            *(float4*)&out_ext[(size_t)node * 256 + col + 4] =
                make_float4(o[4], o[5], o[6], o[7]);
        }
    }
}

// ---------------- launch (forked-capture overlap of CSR + W2 prep with layer 1) ----------------
static cudaStream_t g_side = nullptr;
static cudaEvent_t g_evFork = nullptr, g_evJoin = nullptr;
static int g_stream_tried = 0;

extern "C" void kernel_launch(void* const* d_in, const int* in_sizes, int n_in,
                              void* d_out, int out_size) {
    const float* data = (const float*)d_in[0];
    const int*   src  = (const int*)d_in[1];
    const int*   dst  = (const int*)d_in[2];
    const float* W1   = (const float*)d_in[3];
    const float* al1  = (const float*)d_in[4];
    const float* ar1  = (const float*)d_in[5];
    const float* b1   = (const float*)d_in[6];
    const float* W2   = (const float*)d_in[7];
    const float* al2  = (const float*)d_in[8];
    const float* ar2  = (const float*)d_in[9];
    const float* b2   = (const float*)d_in[10];
    float* out = (float*)d_out;

    __half *dA16 = nullptr, *dW1_16 = nullptr, *dW2_16 = nullptr;
    cudaGetSymbolAddress((void**)&dA16, g_A16);
    cudaGetSymbolAddress((void**)&dW1_16, g_W1_16);
    cudaGetSymbolAddress((void**)&dW2_16, g_W2_16);

    cudaFuncSetAttribute(hgemm_kernel, cudaFuncAttributeMaxDynamicSharedMemorySize, GEMM_SMEM);

    if (!g_stream_tried) {
        g_stream_tried = 1;
        if (cudaStreamCreateWithFlags(&g_side, cudaStreamNonBlocking) != cudaSuccess)
            g_side = nullptr;
        if (g_side) {
            if (cudaEventCreateWithFlags(&g_evFork, cudaEventDisableTiming) != cudaSuccess ||
                cudaEventCreateWithFlags(&g_evJoin, cudaEventDisableTiming) != cudaSuccess) {
                g_side = nullptr;
            }
        }
    }

    dim3 ggrid((N_NODES + 127) / 128, 2);
    const int nA4 = N_NODES * HID / 4;
    const int nW4 = HID * HID / 4;
    const int agrid = N_NODES / 4;

    if (g_side) {
        cudaEventRecord(g_evFork, 0);
        cudaStreamWaitEvent(g_side, g_evFork, 0);

        // side: CSR + W2 convert
        zero_count_kernel<<<(N_NODES + 255) / 256, 256, 0, g_side>>>();
        hist_kernel<<<(N_EDGES + 255) / 256, 256, 0, g_side>>>(dst);
        scan_kernel<<<1, 1024, 0, g_side>>>();
        scatter_kernel<<<(N_EDGES + 255) / 256, 256, 0, g_side>>>(src, dst);
        prep_half_kernel<<<(nW4 + 255) / 256, 256, 0, g_side>>>(W2, dW2_16, nW4);
        cudaEventRecord(g_evJoin, g_side);

        // main: layer-1 path
        prep_half_kernel<<<(nW4 + 255) / 256, 256>>>(W1, dW1_16, nW4);
        prep_half_kernel<<<(nA4 + 255) / 256, 256>>>(data, dA16, nA4);
        hgemm_kernel<<<ggrid, 256, GEMM_SMEM>>>(al1, ar1, dW1_16);

        cudaStreamWaitEvent(0, g_evJoin, 0);
        agg_kernel<0><<<agrid, 256>>>(b1, nullptr);

        hgemm_kernel<<<ggrid, 256, GEMM_SMEM>>>(al2, ar2, dW2_16);
        agg_kernel<1><<<agrid, 256>>>(b2, out);
    } else {
        // serial fallback
        zero_count_kernel<<<(N_NODES + 255) / 256, 256>>>();
        hist_kernel<<<(N_EDGES + 255) / 256, 256>>>(dst);
        scan_kernel<<<1, 1024>>>();
        scatter_kernel<<<(N_EDGES + 255) / 256, 256>>>(src, dst);

        prep_half_kernel<<<(nW4 + 255) / 256, 256>>>(W1, dW1_16, nW4);
        prep_half_kernel<<<(nA4 + 255) / 256, 256>>>(data, dA16, nA4);
        hgemm_kernel<<<ggrid, 256, GEMM_SMEM>>>(al1, ar1, dW1_16);
        agg_kernel<0><<<agrid, 256>>>(b1, nullptr);

        prep_half_kernel<<<(nW4 + 255) / 256, 256>>>(W2, dW2_16, nW4);
        hgemm_kernel<<<ggrid, 256, GEMM_SMEM>>>(al2, ar2, dW2_16);
        agg_kernel<1><<<agrid, 256>>>(b2, out);
    }
}